// round 7
// baseline (speedup 1.0000x reference)
#include <cuda_runtime.h>
#include <cuda_bf16.h>

// Problem: x [64,224,224,32] f32; W_cls [32,4]; b_cls [4].
// out[b] = rot90(x[b], k[b]) with k[b] = argmax(mean_hw(x[b]) @ W + b).
//
// READ-ONCE scheme: each block owns one 16x16-pixel tile (32 KB) of one
// batch. It loads the tile ONCE (coalesced), computes the deterministic
// channel partial-sum, publishes it, and KEEPS the tile in smem. The last
// finisher of the batch computes k[b] and raises flag[b]; then every holder
// scatters its tile to the rotated output position with row-coalesced
// writes. DRAM traffic: 411 MB read + 411 MB write = 822 MB (was 1.23 GB).
//
// Deadlock-free: monotone task counter is batch-major; batch-b holders wait
// only on flag[b], which batch-b holders themselves produce before waiting.

#define BATCH 64
#define HW    224
#define PIX   (HW * HW)        // 50176
#define CH    32
#define TS    16
#define NT    14               // 224/16
#define TILES (NT * NT)        // 196 tiles per batch
#define TOTAL_TASKS (BATCH * TILES)   // 12544
#define GRID_BLOCKS (148 * 6)         // 888 resident (6/SM @ ~33KB smem)

__device__ float4   g_partial[BATCH * TILES * 8];
__device__ int      g_k[BATCH];
__device__ unsigned g_ctr;
__device__ int      g_done[BATCH];
__device__ int      g_flag[BATCH];

__global__ void init_kernel() {
    int t = threadIdx.x;
    if (t == 0) g_ctr = 0u;
    if (t < BATCH) { g_done[t] = 0; g_flag[t] = 0; }
}

__global__ void __launch_bounds__(256, 6) fused_kernel(const float4* __restrict__ x,
                                                       const float*  __restrict__ W_cls,
                                                       const float*  __restrict__ b_cls,
                                                       float4*       __restrict__ out) {
    __shared__ float4 tile[TS * TS * 8];   // 32 KB, held across the wait
    __shared__ float4 sm[8][8];
    __shared__ float  meanv[CH];
    __shared__ int    sh_task;
    __shared__ int    sh_last;
    __shared__ int    sh_k;

    const int t    = threadIdx.x;
    const int lane = t & 31;
    const int warp = t >> 5;
    const int q    = t & 7;

    for (;;) {
        __syncthreads();                   // protect shared state across iters
        if (t == 0) sh_task = (int)atomicAdd(&g_ctr, 1u);
        __syncthreads();
        const int task = sh_task;
        if (task >= TOTAL_TASKS) return;

        const int b    = task / TILES;
        const int tidx = task - b * TILES;
        const int ti   = tidx / NT;
        const int tj   = tidx - ti * NT;
        const int a0   = ti * TS;          // source tile row origin
        const int b0   = tj * TS;          // source tile col origin

        const float4* src_base = x   + (unsigned)b * PIX * 8u;
        float4*       out_base = out + (unsigned)b * PIX * 8u;

        // ---- Phase 1: load tile once (row-coalesced, 2KB segments),
        //      accumulate channel partial sums, stash data in smem. --------
        float4 s = make_float4(0.f, 0.f, 0.f, 0.f);
#pragma unroll
        for (int it = 0; it < 8; ++it) {
            int pix = it * 32 + (t >> 3);          // 0..255
            int r   = pix >> 4;                    // tile row
            int cc  = pix & 15;                    // tile col
            float4 v = __ldg(&src_base[(unsigned)((a0 + r) * HW + (b0 + cc)) * 8u + q]);
            tile[pix * 8 + q] = v;
            s.x += v.x; s.y += v.y; s.z += v.z; s.w += v.w;
        }
#pragma unroll
        for (int off = 8; off <= 16; off <<= 1) {
            s.x += __shfl_xor_sync(0xffffffffu, s.x, off);
            s.y += __shfl_xor_sync(0xffffffffu, s.y, off);
            s.z += __shfl_xor_sync(0xffffffffu, s.z, off);
            s.w += __shfl_xor_sync(0xffffffffu, s.w, off);
        }
        if (lane < 8) sm[warp][lane] = s;
        __syncthreads();

        if (t < 8) {
            float4 acc = sm[0][t];
#pragma unroll
            for (int w = 1; w < 8; ++w) {
                float4 v = sm[w][t];
                acc.x += v.x; acc.y += v.y; acc.z += v.z; acc.w += v.w;
            }
            g_partial[(b * TILES + tidx) * 8 + t] = acc;
            __threadfence();
        }
        __syncthreads();

        if (t == 0) {
            int old = atomicAdd(&g_done[b], 1);
            sh_last = (old == TILES - 1);
        }
        __syncthreads();

        // ---- Phase 2 (last finisher only): mean -> logits -> argmax ------
        if (sh_last) {
            if (t == 0) __threadfence();
            __syncthreads();
            if (t < CH) {
                const int qq = t >> 2, r = t & 3;
                float ssum = 0.f;
                for (int ch = 0; ch < TILES; ++ch) {
                    float4 v = g_partial[(b * TILES + ch) * 8 + qq];
                    ssum += (r == 0) ? v.x : (r == 1) ? v.y : (r == 2) ? v.z : v.w;
                }
                meanv[t] = ssum * (1.0f / (float)PIX);
            }
            __syncthreads();
            if (t == 0) {
                float best = -3.402823466e38f;
                int bi = 0;
#pragma unroll
                for (int o = 0; o < 4; ++o) {
                    float l = __ldg(&b_cls[o]);
#pragma unroll
                    for (int cc = 0; cc < CH; ++cc)
                        l += meanv[cc] * __ldg(&W_cls[cc * 4 + o]);
                    if (l > best) { best = l; bi = o; }   // first-max (jnp.argmax)
                }
                g_k[b] = bi;
                __threadfence();
                atomicExch(&g_flag[b], 1);
            }
        }

        // ---- Phase 3: wait for k[b], then scatter the held tile ----------
        if (t == 0) {
            while (0 == *(volatile int*)&g_flag[b]) __nanosleep(100);
            __threadfence();
            sh_k = g_k[b];
        }
        __syncthreads();
        const int k = sh_k;

        // Output tile origin for source tile (a0,b0) under rot90^k:
        //   k=0: (a0, b0)   k=1: (208-b0, a0)   k=2: (208-a0, 208-b0)
        //   k=3: (b0, 208-a0)
        int i0, j0;
        switch (k) {
            case 0:  i0 = a0;            j0 = b0;            break;
            case 1:  i0 = HW - TS - b0;  j0 = a0;            break;
            case 2:  i0 = HW - TS - a0;  j0 = HW - TS - b0;  break;
            default: i0 = b0;            j0 = HW - TS - a0;  break;
        }

        // Row-coalesced output writes; in-smem transpose/reverse:
        //   k=0: lsi=li,    lsj=lj      k=1: lsi=lj,    lsj=15-li
        //   k=2: lsi=15-li, lsj=15-lj   k=3: lsi=15-lj, lsj=li
#pragma unroll
        for (int it = 0; it < 8; ++it) {
            int pix = it * 32 + (t >> 3);
            int li  = pix >> 4;
            int lj  = pix & 15;
            int lsi, lsj;
            switch (k) {
                case 0:  lsi = li;          lsj = lj;          break;
                case 1:  lsi = lj;          lsj = TS - 1 - li; break;
                case 2:  lsi = TS - 1 - li; lsj = TS - 1 - lj; break;
                default: lsi = TS - 1 - lj; lsj = li;          break;
            }
            __stcs(&out_base[(unsigned)((i0 + li) * HW + (j0 + lj)) * 8u + q],
                   tile[(lsi * TS + lsj) * 8 + q]);
        }
    }
}

extern "C" void kernel_launch(void* const* d_in, const int* in_sizes, int n_in,
                              void* d_out, int out_size) {
    const float4* x     = (const float4*)d_in[0];
    const float*  W_cls = (const float*)d_in[1];
    const float*  b_cls = (const float*)d_in[2];
    float4*       out   = (float4*)d_out;

    init_kernel<<<1, 128>>>();
    fused_kernel<<<GRID_BLOCKS, 256>>>(x, W_cls, b_cls, out);
}

// round 9
// speedup vs baseline: 4.3813x; 4.3813x over previous
#include <cuda_runtime.h>
#include <cuda_bf16.h>

// Problem: x [64,224,224,32] f32; W_cls [32,4]; b_cls [4].
// out[b] = rot90(x[b], k[b]) with k[b] = argmax(mean_hw(x[b]) @ W + b).
//
// R5 structure (best known): persistent fused kernel, atomic work queue of
// 6272 tasks (128 groups of 49), reduce/rotate interleaved with D=6 batch
// delay, grid 1184 (8/SM). R8 changes: (1) no init kernel — the LAST block
// to exit resets all queue state for the next graph replay; (2) rotate
// unroll 4 -> 8 for deeper front-batched load MLP.

#define BATCH 64
#define HW    224
#define PIX   (HW * HW)        // 50176
#define CH    32
#define NCHUNK 49
#define DLY   6
#define TOTAL_TASKS (2 * BATCH * NCHUNK)      // 6272
#define GRID_BLOCKS (148 * 8)                 // 1184

// All queue state must be zero-initialized at load AND restored by the
// last exiting block so the kernel is graph-replayable.
__device__ float4   g_partial[BATCH * NCHUNK * 8];
__device__ int      g_k[BATCH];
__device__ unsigned g_ctr;                    // zero-init at module load
__device__ int      g_done[BATCH];
__device__ int      g_flag[BATCH];
__device__ unsigned g_exit;

// per-k affine coefficients for src offset (float4 units, before +q):
//   k=0: si=i,     sj=j      k=1: si=j,     sj=223-i
//   k=2: si=223-i, sj=223-j  k=3: si=223-j, sj=i
__constant__ int c_A[4] = { HW*8,      -8,      -HW*8,   8      };
__constant__ int c_B[4] = { 8,          HW*8,   -8,      -HW*8  };
__constant__ int c_C[4] = { 0,          223*8,  (223*HW+223)*8, 223*HW*8 };

__global__ void __launch_bounds__(256, 8) fused_kernel(const float4* __restrict__ x,
                                                       const float*  __restrict__ W_cls,
                                                       const float*  __restrict__ b_cls,
                                                       float4*       __restrict__ out) {
    __shared__ float4 sm[8][8];
    __shared__ float  meanv[CH];
    __shared__ int    sh_task;
    __shared__ int    sh_last;
    __shared__ int    sh_k;

    const int t    = threadIdx.x;
    const int lane = t & 31;
    const int warp = t >> 5;
    const int q    = t & 7;

    for (;;) {
        __syncthreads();
        if (t == 0) sh_task = (int)atomicAdd(&g_ctr, 1u);
        __syncthreads();
        const int task = sh_task;
        if (task >= TOTAL_TASKS) break;

        // -------- decode interleaved schedule (delay = DLY batches) --------
        const int g     = task / NCHUNK;
        const int slice = task - g * NCHUNK;
        int is_reduce, b;
        if (g < DLY)             { is_reduce = 1; b = g; }
        else if (g < 128 - DLY)  { int h = g - DLY;
                                   is_reduce = !(h & 1);
                                   b = is_reduce ? (DLY + (h >> 1)) : (h >> 1); }
        else                     { is_reduce = 0; b = (64 - DLY) + (g - (128 - DLY)); }

        if (is_reduce) {
            // ---------------- reduction chunk (order-identical to R1) -------
            const unsigned base = ((unsigned)b * PIX + (unsigned)slice * 1024u) * 8u;

            float4 s = make_float4(0.f, 0.f, 0.f, 0.f);
#pragma unroll 4
            for (int it = 0; it < 32; ++it) {
                unsigned pix = (unsigned)(it * 32 + (t >> 3));
                float4 v = __ldg(&x[base + pix * 8u + q]);
                s.x += v.x; s.y += v.y; s.z += v.z; s.w += v.w;
            }
#pragma unroll
            for (int off = 8; off <= 16; off <<= 1) {
                s.x += __shfl_xor_sync(0xffffffffu, s.x, off);
                s.y += __shfl_xor_sync(0xffffffffu, s.y, off);
                s.z += __shfl_xor_sync(0xffffffffu, s.z, off);
                s.w += __shfl_xor_sync(0xffffffffu, s.w, off);
            }
            if (lane < 8) sm[warp][lane] = s;
            __syncthreads();

            if (t < 8) {
                float4 acc = sm[0][t];
#pragma unroll
                for (int w = 1; w < 8; ++w) {
                    float4 v = sm[w][t];
                    acc.x += v.x; acc.y += v.y; acc.z += v.z; acc.w += v.w;
                }
                g_partial[(b * NCHUNK + slice) * 8 + t] = acc;
                __threadfence();
            }
            __syncthreads();

            if (t == 0) {
                int old = atomicAdd(&g_done[b], 1);
                sh_last = (old == NCHUNK - 1);
            }
            __syncthreads();

            if (sh_last) {
                if (t == 0) __threadfence();
                __syncthreads();
                if (t < CH) {
                    const int qq = t >> 2, r = t & 3;
                    float ssum = 0.f;
                    for (int ch = 0; ch < NCHUNK; ++ch) {
                        float4 v = g_partial[(b * NCHUNK + ch) * 8 + qq];
                        ssum += (r == 0) ? v.x : (r == 1) ? v.y : (r == 2) ? v.z : v.w;
                    }
                    meanv[t] = ssum * (1.0f / (float)PIX);
                }
                __syncthreads();
                if (t == 0) {
                    float best = -3.402823466e38f;
                    int bi = 0;
#pragma unroll
                    for (int o = 0; o < 4; ++o) {
                        float l = __ldg(&b_cls[o]);
#pragma unroll
                        for (int cc = 0; cc < CH; ++cc)
                            l += meanv[cc] * __ldg(&W_cls[cc * 4 + o]);
                        if (l > best) { best = l; bi = o; }  // first-max (jnp.argmax)
                    }
                    g_k[b] = bi;
                    __threadfence();
                    atomicExch(&g_flag[b], 1);
                }
            }
        } else {
            // ---------------- rotation slice (affine-incremental) ----------
            if (t == 0) {
                while (0 == *(volatile int*)&g_flag[b]) __nanosleep(100);
                __threadfence();
                sh_k = g_k[b];
            }
            __syncthreads();
            const int k = sh_k;
            const int A = c_A[k], Bc = c_B[k];

            const float4* src_base = x   + (unsigned)b * PIX * 8u;
            float4*       out_base = out + (unsigned)b * PIX * 8u;

            int pix0 = slice * 1024 + (t >> 3);
            int i = pix0 / HW;
            int j = pix0 - i * HW;
            int soff = A * i + Bc * j + c_C[k] + q;   // src float4 offset
            int doff = pix0 * 8 + q;                  // dst float4 offset
            const int stepB   = 32 * Bc;
            const int wrapAdj = A - HW * Bc;

#pragma unroll 8
            for (int it = 0; it < 32; ++it) {
                float4 v = __ldg(&src_base[soff]);    // normal caching
                __stcs(&out_base[doff], v);           // streaming store
                doff += 32 * 8;
                j += 32; soff += stepB;
                if (j >= HW) { j -= HW; soff += wrapAdj; }
            }
        }
    }

    // ---- self-reset for next graph replay: last block out cleans up ------
    __syncthreads();
    if (t == 0) {
        unsigned me = atomicAdd(&g_exit, 1u);
        if (me == GRID_BLOCKS - 1) {
            for (int i = 0; i < BATCH; ++i) { g_done[i] = 0; g_flag[i] = 0; }
            g_ctr  = 0u;
            g_exit = 0u;
            __threadfence();
        }
    }
}

extern "C" void kernel_launch(void* const* d_in, const int* in_sizes, int n_in,
                              void* d_out, int out_size) {
    const float4* x     = (const float4*)d_in[0];
    const float*  W_cls = (const float*)d_in[1];
    const float*  b_cls = (const float*)d_in[2];
    float4*       out   = (float4*)d_out;

    fused_kernel<<<GRID_BLOCKS, 256>>>(x, W_cls, b_cls, out);
}